// round 15
// baseline (speedup 1.0000x reference)
#include <cuda_runtime.h>

#define NN   100000
#define EE   3200000
#define FIN  512
#define HID  16
#define CC   7
#define SRC  128   // per-node CSR slab capacity (degree ~ Poisson(32), max ~65)

// ---- static scratch ----
__device__ __align__(16) float g_t1[NN * HID];  // (x@W1)*dinv[row]
__device__ __align__(16) float g_t2[NN * 8];    // (h@W2)*dinv[row], padded to 8
__device__ int g_cnt[NN];                        // in-degree (excl. self loop)
__device__ int g_srow[(size_t)NN * SRC];         // fixed-slab CSR: sources per dest

__device__ __forceinline__ void ffma2(unsigned long long& d,
                                      unsigned long long a,
                                      unsigned long long b) {
    asm("fma.rn.f32x2 %0, %1, %2, %0;" : "+l"(d) : "l"(a), "l"(b));
}
__device__ __forceinline__ unsigned long long pack2(float lo, float hi) {
    unsigned long long r;
    asm("mov.b64 %0, {%1, %2};" : "=l"(r) : "f"(lo), "f"(hi));
    return r;
}
__device__ __forceinline__ float2 unpack2(unsigned long long v) {
    float2 r;
    asm("mov.b64 {%0, %1}, %2;" : "=f"(r.x), "=f"(r.y) : "l"(v));
    return r;
}
__device__ __forceinline__ void cp_async16(unsigned smem_addr, const void* g) {
    asm volatile("cp.async.cg.shared.global [%0], [%1], 16;" :: "r"(smem_addr), "l"(g));
}
__device__ __forceinline__ void cp_commit() { asm volatile("cp.async.commit_group;"); }
template <int N> __device__ __forceinline__ void cp_wait() {
    asm volatile("cp.async.wait_group %0;" :: "n"(N));
}

// ---------------- init: zero counters (vectorized; NN % 4 == 0) ----------------
__global__ void k_init() {
    int i = blockIdx.x * blockDim.x + threadIdx.x;
    if (i < NN / 4) ((int4*)g_cnt)[i] = make_int4(0, 0, 0, 0);
}

// ---------------- single edge pass: count + scatter into fixed slabs ----------------
__global__ void k_scatter(const int* __restrict__ row, const int* __restrict__ col) {
    int e = blockIdx.x * blockDim.x + threadIdx.x;
    if (e >= EE) return;
    int c = __ldcs(&col[e]);
    int r = __ldcs(&row[e]);
    int p = atomicAdd(&g_cnt[c], 1);
    if (p < SRC) __stcs(&g_srow[(size_t)c * SRC + p], r);
}

// ---------------- layer 1 GEMM: RB=256, 256 thr (4 rows/thread), 3-stage ring ----
#define RB  256
#define KC  32
#define NCH (FIN / KC)
#define XCH (RB * KC)
#define WCH (KC * HID)

__global__ void __launch_bounds__(256) k_gemm1(const float* __restrict__ x,
                                               const float* __restrict__ W1) {
    extern __shared__ float smem[];
    float* xs = smem;
    float* ws = smem + 3 * XCH;

    const int t  = threadIdx.x;
    const int r0 = blockIdx.x * RB;

    const int j     = t & 7;       // 16B granule within 128B row
    const int rbase = t >> 3;      // 0..31

    unsigned xs_base = (unsigned)__cvta_generic_to_shared(xs);
    unsigned ws_base = (unsigned)__cvta_generic_to_shared(ws);

#pragma unroll
    for (int s = 0; s < 3; s++) {
        const int k0 = s * KC;
        unsigned xdst = xs_base + s * (XCH * 4);
#pragma unroll
        for (int p = 0; p < 8; p++) {
            int r  = rbase + 32 * p;
            int gr = min(r0 + r, NN - 1);
            cp_async16(xdst + r * 128 + ((j ^ ((r >> 2) & 7)) * 16),
                       x + (size_t)gr * FIN + k0 + 4 * j);
        }
        if (t < WCH / 4)
            cp_async16(ws_base + s * (WCH * 4) + t * 16, W1 + k0 * HID + t * 4);
        cp_commit();
    }

    const int rg  = t >> 2;        // 0..63
    const int cg4 = (t & 3) * 4;
    const int rb4 = rg * 4;
    const int swz = rg & 7;

    unsigned long long acc[4][2] = {{0,0},{0,0},{0,0},{0,0}};

    for (int kc = 0; kc < NCH; kc++) {
        int rem = NCH - 1 - kc;
        if (rem >= 2) cp_wait<2>(); else if (rem == 1) cp_wait<1>(); else cp_wait<0>();
        __syncthreads();

        const int stage = kc % 3;
        const float* xb = xs + stage * XCH;
        const float* wk = ws + stage * WCH;

#pragma unroll
        for (int q = 0; q < 8; q++) {
            const int pos4 = (q ^ swz) << 2;
            float4 xa[4];
#pragma unroll
            for (int i = 0; i < 4; i++)
                xa[i] = *(const float4*)&xb[(rb4 + i) * KC + pos4];
#pragma unroll
            for (int kk = 0; kk < 4; kk++) {
                ulonglong2 wp = *(const ulonglong2*)&wk[(4 * q + kk) * HID + cg4];
#pragma unroll
                for (int i = 0; i < 4; i++) {
                    float xv = (&xa[i].x)[kk];
                    unsigned long long pv = pack2(xv, xv);
                    ffma2(acc[i][0], pv, wp.x);
                    ffma2(acc[i][1], pv, wp.y);
                }
            }
        }

        if (kc + 3 < NCH) {
            __syncthreads();
            const int k0 = (kc + 3) * KC;
            unsigned xdst = xs_base + (kc % 3) * (XCH * 4);
#pragma unroll
            for (int p = 0; p < 8; p++) {
                int r  = rbase + 32 * p;
                int gr = min(r0 + r, NN - 1);
                cp_async16(xdst + r * 128 + ((j ^ ((r >> 2) & 7)) * 16),
                           x + (size_t)gr * FIN + k0 + 4 * j);
            }
            if (t < WCH / 4)
                cp_async16(ws_base + (kc % 3) * (WCH * 4) + t * 16,
                           W1 + k0 * HID + t * 4);
            cp_commit();
        }
    }

    // epilogue: scale by dinv[row], store messages
#pragma unroll
    for (int rr = 0; rr < 4; rr++) {
        int r = r0 + rb4 + rr;
        if (r >= NN) continue;
        float di = rsqrtf((float)(g_cnt[r] + 1));
        float2 pa = unpack2(acc[rr][0]);
        float2 pb = unpack2(acc[rr][1]);
        *(float4*)&g_t1[(size_t)r * HID + cg4] =
            make_float4(pa.x * di, pa.y * di, pb.x * di, pb.y * di);
    }
}

// ---------------- layer 1 aggregation + bias/relu + redundancy-free L2 transform ----
// warp/node; comp = lane&3 (float4 quarter), sub = lane>>2 (edge slot / output class)
__global__ void __launch_bounds__(256) k_agg1(float* __restrict__ outh,
                                              const float* __restrict__ b1,
                                              const float* __restrict__ W2) {
    int w = (blockIdx.x * blockDim.x + threadIdx.x) >> 5;
    if (w >= NN) return;
    int lane = threadIdx.x & 31;
    int comp = lane & 3;
    int sub  = lane >> 2;
    int cnt  = min(g_cnt[w], SRC);
    const int* sr = g_srow + (size_t)w * SRC;
    const float4* t1v = (const float4*)g_t1;

    // stage first 32 edge indices with ONE coalesced load
    int myidx = (lane < cnt) ? __ldg(&sr[lane]) : 0;

    float4 a[4];
    a[0] = (sub == 0) ? t1v[(size_t)w * 4 + comp] : make_float4(0, 0, 0, 0);
    a[1] = make_float4(0, 0, 0, 0);
    a[2] = make_float4(0, 0, 0, 0);
    a[3] = make_float4(0, 0, 0, 0);

#pragma unroll
    for (int k = 0; k < 4; k++) {
        int p   = sub + 8 * k;                         // < 32 always
        int idx = __shfl_sync(0xffffffffu, myidx, p);
        if (p < cnt) {
            float4 v = t1v[(size_t)idx * 4 + comp];
            a[k].x += v.x; a[k].y += v.y; a[k].z += v.z; a[k].w += v.w;
        }
    }
    for (int p = 32 + sub; p < cnt; p += 8) {          // tail (deg > 32)
        float4 v = t1v[(size_t)__ldg(&sr[p]) * 4 + comp];
        a[0].x += v.x; a[0].y += v.y; a[0].z += v.z; a[0].w += v.w;
    }
    a[0].x += a[1].x + a[2].x + a[3].x;
    a[0].y += a[1].y + a[2].y + a[3].y;
    a[0].z += a[1].z + a[2].z + a[3].z;
    a[0].w += a[1].w + a[2].w + a[3].w;

    // butterfly over sub bits -> every lane holds the full sums for its comp
#pragma unroll
    for (int m = 16; m >= 4; m >>= 1) {
        a[0].x += __shfl_xor_sync(0xffffffffu, a[0].x, m);
        a[0].y += __shfl_xor_sync(0xffffffffu, a[0].y, m);
        a[0].z += __shfl_xor_sync(0xffffffffu, a[0].z, m);
        a[0].w += __shfl_xor_sync(0xffffffffu, a[0].w, m);
    }

    float di = rsqrtf((float)(cnt + 1));
    float h0 = fmaxf(fmaf(a[0].x, di, __ldg(&b1[4 * comp + 0])), 0.0f);
    float h1 = fmaxf(fmaf(a[0].y, di, __ldg(&b1[4 * comp + 1])), 0.0f);
    float h2 = fmaxf(fmaf(a[0].z, di, __ldg(&b1[4 * comp + 2])), 0.0f);
    float h3 = fmaxf(fmaf(a[0].w, di, __ldg(&b1[4 * comp + 3])), 0.0f);
    if (sub == 0)
        ((float4*)outh)[(size_t)w * 4 + comp] = make_float4(h0, h1, h2, h3);

    // redundancy-free transform: lane (sub,comp) computes partial of tv[jj=sub]
    float tv = 0.0f;
    if (sub < CC) {
        tv =            h0 * __ldg(&W2[(4 * comp + 0) * CC + sub]);
        tv = fmaf(h1, __ldg(&W2[(4 * comp + 1) * CC + sub]), tv);
        tv = fmaf(h2, __ldg(&W2[(4 * comp + 2) * CC + sub]), tv);
        tv = fmaf(h3, __ldg(&W2[(4 * comp + 3) * CC + sub]), tv);
    }
    tv += __shfl_xor_sync(0xffffffffu, tv, 1);
    tv += __shfl_xor_sync(0xffffffffu, tv, 2);
    if (comp == 0)
        g_t2[(size_t)w * 8 + sub] = (sub < CC) ? tv * di : 0.0f;
}

// ---------------- layer 2 aggregation + output: HALF-WARP per node ----------------
// lane16 = lane&15; comp = lane16&1 (float4 half), sub = lane16>>1 (edge slot 0..7)
__global__ void __launch_bounds__(256) k_agg2(const float* __restrict__ b2,
                                              float* __restrict__ outz) {
    int w = (blockIdx.x * blockDim.x + threadIdx.x) >> 4;  // half-warp id = node
    if (w >= NN) return;
    int l16  = threadIdx.x & 15;
    int comp = l16 & 1;
    int sub  = l16 >> 1;   // 0..7
    int cnt  = min(g_cnt[w], SRC);
    const int* sr = g_srow + (size_t)w * SRC;
    const float4* t2v = (const float4*)g_t2;

    // stage first 16 edge indices (one coalesced load per warp = 2 nodes)
    int myidx = (l16 < cnt) ? __ldg(&sr[l16]) : 0;

    float4 a0 = (sub == 0) ? t2v[(size_t)w * 2 + comp] : make_float4(0, 0, 0, 0);
    float4 a1 = make_float4(0, 0, 0, 0);

#pragma unroll
    for (int k = 0; k < 2; k++) {
        int p   = sub + 8 * k;                             // < 16 always
        int idx = __shfl_sync(0xffffffffu, myidx, p, 16);  // segment-local
        if (p < cnt) {
            float4 v = t2v[(size_t)idx * 2 + comp];
            if (k == 0) { a0.x += v.x; a0.y += v.y; a0.z += v.z; a0.w += v.w; }
            else        { a1.x += v.x; a1.y += v.y; a1.z += v.z; a1.w += v.w; }
        }
    }
    for (int p = 16 + sub; p < cnt; p += 8) {  // tail: sr[16+sub..] = 1 sector
        float4 v = t2v[(size_t)__ldg(&sr[p]) * 2 + comp];
        a0.x += v.x; a0.y += v.y; a0.z += v.z; a0.w += v.w;
    }
    a0.x += a1.x; a0.y += a1.y; a0.z += a1.z; a0.w += a1.w;

    // butterfly over sub bits (lane bits 1..3) — masks stay inside the half-warp
#pragma unroll
    for (int m = 8; m >= 2; m >>= 1) {
        a0.x += __shfl_xor_sync(0xffffffffu, a0.x, m);
        a0.y += __shfl_xor_sync(0xffffffffu, a0.y, m);
        a0.z += __shfl_xor_sync(0xffffffffu, a0.z, m);
        a0.w += __shfl_xor_sync(0xffffffffu, a0.w, m);
    }
    if (sub == 0) {
        float di = rsqrtf((float)(cnt + 1));
        if (comp == 0) {
            outz[(size_t)w * CC + 0] = fmaf(di, a0.x, __ldg(&b2[0]));
            outz[(size_t)w * CC + 1] = fmaf(di, a0.y, __ldg(&b2[1]));
            outz[(size_t)w * CC + 2] = fmaf(di, a0.z, __ldg(&b2[2]));
            outz[(size_t)w * CC + 3] = fmaf(di, a0.w, __ldg(&b2[3]));
        } else {
            outz[(size_t)w * CC + 4] = fmaf(di, a0.x, __ldg(&b2[4]));
            outz[(size_t)w * CC + 5] = fmaf(di, a0.y, __ldg(&b2[5]));
            outz[(size_t)w * CC + 6] = fmaf(di, a0.z, __ldg(&b2[6]));
        }
    }
}

extern "C" void kernel_launch(void* const* d_in, const int* in_sizes, int n_in,
                              void* d_out, int out_size) {
    const float* x  = (const float*)d_in[0];
    const float* W1 = (const float*)d_in[1];
    const float* b1 = (const float*)d_in[2];
    const float* W2 = (const float*)d_in[3];
    const float* b2 = (const float*)d_in[4];
    const int*   ei = (const int*)d_in[5];
    const int* row = ei;
    const int* col = ei + EE;

    float* out  = (float*)d_out;
    float* outh = out;                     // [N, 16]
    float* outz = out + (size_t)NN * HID;  // [N, 7]

    const int smem_bytes = (3 * XCH + 3 * WCH) * 4;  // 102 KB
    cudaFuncSetAttribute(k_gemm1, cudaFuncAttributeMaxDynamicSharedMemorySize,
                         smem_bytes);

    k_init   <<<(NN / 4 + 511) / 512, 512>>>();
    k_scatter<<<(EE + 255) / 256, 256>>>(row, col);
    k_gemm1  <<<(NN + RB - 1) / RB, 256, smem_bytes>>>(x, W1);
    k_agg1   <<<(NN * 32 + 255) / 256, 256>>>(outh, b1, W2);
    k_agg2   <<<(NN * 16 + 255) / 256, 256>>>(b2, outz);
}

// round 16
// speedup vs baseline: 1.0402x; 1.0402x over previous
#include <cuda_runtime.h>

#define NN   100000
#define EE   3200000
#define FIN  512
#define HID  16
#define CC   7
#define SRC  128   // per-node CSR slab capacity (degree ~ Poisson(32), max ~65)

// ---- static scratch ----
__device__ __align__(16) float g_t1[NN * HID];  // (x@W1)*dinv[row]
__device__ __align__(16) float g_t2[NN * 8];    // (h@W2)*dinv[row], padded to 8
__device__ int g_cnt[NN];                        // in-degree (excl. self loop)
__device__ int g_srow[(size_t)NN * SRC];         // fixed-slab CSR: sources per dest

__device__ __forceinline__ void ffma2(unsigned long long& d,
                                      unsigned long long a,
                                      unsigned long long b) {
    asm("fma.rn.f32x2 %0, %1, %2, %0;" : "+l"(d) : "l"(a), "l"(b));
}
__device__ __forceinline__ unsigned long long pack2(float lo, float hi) {
    unsigned long long r;
    asm("mov.b64 %0, {%1, %2};" : "=l"(r) : "f"(lo), "f"(hi));
    return r;
}
__device__ __forceinline__ float2 unpack2(unsigned long long v) {
    float2 r;
    asm("mov.b64 {%0, %1}, %2;" : "=f"(r.x), "=f"(r.y) : "l"(v));
    return r;
}
__device__ __forceinline__ void cp_async16(unsigned smem_addr, const void* g) {
    asm volatile("cp.async.cg.shared.global [%0], [%1], 16;" :: "r"(smem_addr), "l"(g));
}
__device__ __forceinline__ void cp_commit() { asm volatile("cp.async.commit_group;"); }
template <int N> __device__ __forceinline__ void cp_wait() {
    asm volatile("cp.async.wait_group %0;" :: "n"(N));
}

// ---------------- init: zero counters (vectorized; NN % 4 == 0) ----------------
__global__ void k_init() {
    int i = blockIdx.x * blockDim.x + threadIdx.x;
    if (i < NN / 4) ((int4*)g_cnt)[i] = make_int4(0, 0, 0, 0);
}

// ---------------- single edge pass: count + scatter into fixed slabs ----------------
// Fires the PDL trigger at entry so the following GEMM can start its (independent)
// mainloop concurrently; the GEMM grid-syncs before touching g_cnt.
__global__ void k_scatter(const int* __restrict__ row, const int* __restrict__ col) {
    cudaTriggerProgrammaticLaunchCompletion();
    int e = blockIdx.x * blockDim.x + threadIdx.x;
    if (e >= EE) return;
    int c = __ldcs(&col[e]);
    int r = __ldcs(&row[e]);
    int p = atomicAdd(&g_cnt[c], 1);
    if (p < SRC) __stcs(&g_srow[(size_t)c * SRC + p], r);
}

// ---------------- layer 1 GEMM: RB=256, 128 thr (8 rows/thread), 3-stage ring ----
#define RB  256
#define KC  32
#define NCH (FIN / KC)
#define XCH (RB * KC)
#define WCH (KC * HID)

__global__ void __launch_bounds__(128) k_gemm1(const float* __restrict__ x,
                                               const float* __restrict__ W1) {
    extern __shared__ float smem[];
    float* xs = smem;
    float* ws = smem + 3 * XCH;

    const int t  = threadIdx.x;
    const int r0 = blockIdx.x * RB;

    const int j     = t & 7;
    const int rbase = t >> 3;

    unsigned xs_base = (unsigned)__cvta_generic_to_shared(xs);
    unsigned ws_base = (unsigned)__cvta_generic_to_shared(ws);

#pragma unroll
    for (int s = 0; s < 3; s++) {
        const int k0 = s * KC;
        unsigned xdst = xs_base + s * (XCH * 4);
#pragma unroll
        for (int p = 0; p < 16; p++) {
            int r  = rbase + 16 * p;
            int gr = min(r0 + r, NN - 1);
            cp_async16(xdst + r * 128 + ((j ^ ((r >> 2) & 7)) * 16),
                       x + (size_t)gr * FIN + k0 + 4 * j);
        }
        cp_async16(ws_base + s * (WCH * 4) + t * 16, W1 + k0 * HID + t * 4);
        cp_commit();
    }

    const int rg  = t >> 2;
    const int cg4 = (t & 3) * 4;
    const int rb4 = rg * 4;
    const int swz = rg & 7;

    unsigned long long acc[8][2] = {{0,0},{0,0},{0,0},{0,0},{0,0},{0,0},{0,0},{0,0}};

    for (int kc = 0; kc < NCH; kc++) {
        int rem = NCH - 1 - kc;
        if (rem >= 2) cp_wait<2>(); else if (rem == 1) cp_wait<1>(); else cp_wait<0>();
        __syncthreads();

        const int stage = kc % 3;
        const float* xb = xs + stage * XCH;
        const float* wk = ws + stage * WCH;

#pragma unroll
        for (int q = 0; q < 8; q++) {
            const int pos4 = (q ^ swz) << 2;
            float4 xa[8];
#pragma unroll
            for (int i = 0; i < 4; i++) {
                xa[i]     = *(const float4*)&xb[(rb4 + i) * KC + pos4];
                xa[4 + i] = *(const float4*)&xb[(rb4 + 128 + i) * KC + pos4];
            }
#pragma unroll
            for (int kk = 0; kk < 4; kk++) {
                ulonglong2 wp = *(const ulonglong2*)&wk[(4 * q + kk) * HID + cg4];
#pragma unroll
                for (int i = 0; i < 8; i++) {
                    float xv = (&xa[i].x)[kk];
                    unsigned long long pv = pack2(xv, xv);
                    ffma2(acc[i][0], pv, wp.x);
                    ffma2(acc[i][1], pv, wp.y);
                }
            }
        }

        if (kc + 3 < NCH) {
            __syncthreads();
            const int k0 = (kc + 3) * KC;
            unsigned xdst = xs_base + (kc % 3) * (XCH * 4);
#pragma unroll
            for (int p = 0; p < 16; p++) {
                int r  = rbase + 16 * p;
                int gr = min(r0 + r, NN - 1);
                cp_async16(xdst + r * 128 + ((j ^ ((r >> 2) & 7)) * 16),
                           x + (size_t)gr * FIN + k0 + 4 * j);
            }
            cp_async16(ws_base + (kc % 3) * (WCH * 4) + t * 16, W1 + k0 * HID + t * 4);
            cp_commit();
        }
    }

    // Wait for k_scatter's writes (g_cnt) to be visible before the epilogue.
    cudaGridDependencySynchronize();

    // epilogue: scale by dinv[row], store messages
#pragma unroll
    for (int rr = 0; rr < 8; rr++) {
        int r = r0 + rb4 + (rr & 3) + ((rr >> 2) << 7);
        if (r >= NN) continue;
        float di = rsqrtf((float)(g_cnt[r] + 1));
        float2 pa = unpack2(acc[rr][0]);
        float2 pb = unpack2(acc[rr][1]);
        *(float4*)&g_t1[(size_t)r * HID + cg4] =
            make_float4(pa.x * di, pa.y * di, pb.x * di, pb.y * di);
    }
}

// ---------------- layer 1 aggregation + bias/relu + redundancy-free L2 transform ----
// warp/node; comp = lane&3 (float4 quarter), sub = lane>>2 (edge slot / output class)
__global__ void __launch_bounds__(256) k_agg1(float* __restrict__ outh,
                                              const float* __restrict__ b1,
                                              const float* __restrict__ W2) {
    int w = (blockIdx.x * blockDim.x + threadIdx.x) >> 5;
    if (w >= NN) return;
    int lane = threadIdx.x & 31;
    int comp = lane & 3;
    int sub  = lane >> 2;
    int cnt  = min(g_cnt[w], SRC);
    const int* sr = g_srow + (size_t)w * SRC;
    const float4* t1v = (const float4*)g_t1;

    // stage first 32 edge indices with ONE coalesced load
    int myidx = (lane < cnt) ? __ldg(&sr[lane]) : 0;

    float4 a[4];
    a[0] = (sub == 0) ? t1v[(size_t)w * 4 + comp] : make_float4(0, 0, 0, 0);
    a[1] = make_float4(0, 0, 0, 0);
    a[2] = make_float4(0, 0, 0, 0);
    a[3] = make_float4(0, 0, 0, 0);

#pragma unroll
    for (int k = 0; k < 4; k++) {
        int p   = sub + 8 * k;                         // < 32 always
        int idx = __shfl_sync(0xffffffffu, myidx, p);
        if (p < cnt) {
            float4 v = t1v[(size_t)idx * 4 + comp];
            a[k].x += v.x; a[k].y += v.y; a[k].z += v.z; a[k].w += v.w;
        }
    }
    for (int p = 32 + sub; p < cnt; p += 8) {          // tail (deg > 32)
        float4 v = t1v[(size_t)__ldg(&sr[p]) * 4 + comp];
        a[0].x += v.x; a[0].y += v.y; a[0].z += v.z; a[0].w += v.w;
    }
    a[0].x += a[1].x + a[2].x + a[3].x;
    a[0].y += a[1].y + a[2].y + a[3].y;
    a[0].z += a[1].z + a[2].z + a[3].z;
    a[0].w += a[1].w + a[2].w + a[3].w;

    // butterfly over sub bits -> every lane holds the full sums for its comp
#pragma unroll
    for (int m = 16; m >= 4; m >>= 1) {
        a[0].x += __shfl_xor_sync(0xffffffffu, a[0].x, m);
        a[0].y += __shfl_xor_sync(0xffffffffu, a[0].y, m);
        a[0].z += __shfl_xor_sync(0xffffffffu, a[0].z, m);
        a[0].w += __shfl_xor_sync(0xffffffffu, a[0].w, m);
    }

    float di = rsqrtf((float)(cnt + 1));
    float h0 = fmaxf(fmaf(a[0].x, di, __ldg(&b1[4 * comp + 0])), 0.0f);
    float h1 = fmaxf(fmaf(a[0].y, di, __ldg(&b1[4 * comp + 1])), 0.0f);
    float h2 = fmaxf(fmaf(a[0].z, di, __ldg(&b1[4 * comp + 2])), 0.0f);
    float h3 = fmaxf(fmaf(a[0].w, di, __ldg(&b1[4 * comp + 3])), 0.0f);
    if (sub == 0)
        ((float4*)outh)[(size_t)w * 4 + comp] = make_float4(h0, h1, h2, h3);

    // redundancy-free transform: lane (sub,comp) computes partial of tv[jj=sub]
    float tv = 0.0f;
    if (sub < CC) {
        tv =            h0 * __ldg(&W2[(4 * comp + 0) * CC + sub]);
        tv = fmaf(h1, __ldg(&W2[(4 * comp + 1) * CC + sub]), tv);
        tv = fmaf(h2, __ldg(&W2[(4 * comp + 2) * CC + sub]), tv);
        tv = fmaf(h3, __ldg(&W2[(4 * comp + 3) * CC + sub]), tv);
    }
    tv += __shfl_xor_sync(0xffffffffu, tv, 1);
    tv += __shfl_xor_sync(0xffffffffu, tv, 2);
    if (comp == 0)
        g_t2[(size_t)w * 8 + sub] = (sub < CC) ? tv * di : 0.0f;
}

// ---------------- layer 2 aggregation + output: HALF-WARP per node ----------------
// lane16 = lane&15; comp = lane16&1 (float4 half), sub = lane16>>1 (edge slot 0..7)
__global__ void __launch_bounds__(256) k_agg2(const float* __restrict__ b2,
                                              float* __restrict__ outz) {
    int w = (blockIdx.x * blockDim.x + threadIdx.x) >> 4;  // half-warp id = node
    if (w >= NN) return;
    int l16  = threadIdx.x & 15;
    int comp = l16 & 1;
    int sub  = l16 >> 1;   // 0..7
    int cnt  = min(g_cnt[w], SRC);
    const int* sr = g_srow + (size_t)w * SRC;
    const float4* t2v = (const float4*)g_t2;

    // stage first 16 edge indices (one coalesced load per warp = 2 nodes)
    int myidx = (l16 < cnt) ? __ldg(&sr[l16]) : 0;

    float4 a0 = (sub == 0) ? t2v[(size_t)w * 2 + comp] : make_float4(0, 0, 0, 0);
    float4 a1 = make_float4(0, 0, 0, 0);

#pragma unroll
    for (int k = 0; k < 2; k++) {
        int p   = sub + 8 * k;                             // < 16 always
        int idx = __shfl_sync(0xffffffffu, myidx, p, 16);  // segment-local
        if (p < cnt) {
            float4 v = t2v[(size_t)idx * 2 + comp];
            if (k == 0) { a0.x += v.x; a0.y += v.y; a0.z += v.z; a0.w += v.w; }
            else        { a1.x += v.x; a1.y += v.y; a1.z += v.z; a1.w += v.w; }
        }
    }
    for (int p = 16 + sub; p < cnt; p += 8) {  // tail: sr[16+sub..] = 1 sector
        float4 v = t2v[(size_t)__ldg(&sr[p]) * 2 + comp];
        a0.x += v.x; a0.y += v.y; a0.z += v.z; a0.w += v.w;
    }
    a0.x += a1.x; a0.y += a1.y; a0.z += a1.z; a0.w += a1.w;

    // butterfly over sub bits (lane bits 1..3) — masks stay inside the half-warp
#pragma unroll
    for (int m = 8; m >= 2; m >>= 1) {
        a0.x += __shfl_xor_sync(0xffffffffu, a0.x, m);
        a0.y += __shfl_xor_sync(0xffffffffu, a0.y, m);
        a0.z += __shfl_xor_sync(0xffffffffu, a0.z, m);
        a0.w += __shfl_xor_sync(0xffffffffu, a0.w, m);
    }
    if (sub == 0) {
        float di = rsqrtf((float)(cnt + 1));
        if (comp == 0) {
            outz[(size_t)w * CC + 0] = fmaf(di, a0.x, __ldg(&b2[0]));
            outz[(size_t)w * CC + 1] = fmaf(di, a0.y, __ldg(&b2[1]));
            outz[(size_t)w * CC + 2] = fmaf(di, a0.z, __ldg(&b2[2]));
            outz[(size_t)w * CC + 3] = fmaf(di, a0.w, __ldg(&b2[3]));
        } else {
            outz[(size_t)w * CC + 4] = fmaf(di, a0.x, __ldg(&b2[4]));
            outz[(size_t)w * CC + 5] = fmaf(di, a0.y, __ldg(&b2[5]));
            outz[(size_t)w * CC + 6] = fmaf(di, a0.z, __ldg(&b2[6]));
        }
    }
}

extern "C" void kernel_launch(void* const* d_in, const int* in_sizes, int n_in,
                              void* d_out, int out_size) {
    const float* x  = (const float*)d_in[0];
    const float* W1 = (const float*)d_in[1];
    const float* b1 = (const float*)d_in[2];
    const float* W2 = (const float*)d_in[3];
    const float* b2 = (const float*)d_in[4];
    const int*   ei = (const int*)d_in[5];
    const int* row = ei;
    const int* col = ei + EE;

    float* out  = (float*)d_out;
    float* outh = out;                     // [N, 16]
    float* outz = out + (size_t)NN * HID;  // [N, 7]

    const int smem_bytes = (3 * XCH + 3 * WCH) * 4;  // 102 KB
    cudaFuncSetAttribute(k_gemm1, cudaFuncAttributeMaxDynamicSharedMemorySize,
                         smem_bytes);

    k_init   <<<(NN / 4 + 511) / 512, 512>>>();
    k_scatter<<<(EE + 255) / 256, 256>>>(row, col);

    // PDL launch: gemm1's mainloop overlaps k_scatter; grid-sync guards g_cnt.
    cudaLaunchAttribute attrs[1];
    attrs[0].id = cudaLaunchAttributeProgrammaticStreamSerialization;
    attrs[0].val.programmaticStreamSerializationAllowed = 1;
    cudaLaunchConfig_t cfg = {};
    cfg.gridDim = dim3((NN + RB - 1) / RB);
    cfg.blockDim = dim3(128);
    cfg.dynamicSmemBytes = smem_bytes;
    cfg.stream = 0;
    cfg.attrs = attrs;
    cfg.numAttrs = 1;
    cudaLaunchKernelEx(&cfg, k_gemm1, x, W1);

    k_agg1<<<(NN * 32 + 255) / 256, 256>>>(outh, b1, W2);
    k_agg2<<<(NN * 16 + 255) / 256, 256>>>(b2, outz);
}